// round 1
// baseline (speedup 1.0000x reference)
#include <cuda_runtime.h>
#include <cuda_bf16.h>
#include <cstddef>

// Problem constants
#define M_X   8192
#define K_IN  1024      // 32*32
#define N_OUT 4096      // 64*64
#define R     16        // ranks
#define RQ    256       // (a,q) contraction size = 16*16

// Scratch (device globals; allocation-free per harness rules)
__device__ float g_T2[1024 * 256];     // [i0*32+i1][a*16+q]         (1 MB)
__device__ float g_M23[4096 * 256];    // [o0*64+o1][a*16+q]         (4 MB)
__device__ float g_W[1024 * 4096];     // row-major == reference flat (16 MB)

// ---------------------------------------------------------------------------
// T2[a,i0,i1,q] = sum_b core0[a,i0,b] * core1[b,i1,q]
// stored as g_T2[(i0*32+i1)*256 + a*16+q]
// core0: (16,32,16) strides a:512, i0:16, b:1
// core1: (16,32,16) strides b:512, i1:16, q:1
__global__ void t2_kernel(const float* __restrict__ c0, const float* __restrict__ c1) {
    int idx = blockIdx.x * blockDim.x + threadIdx.x;   // 1024*256 threads
    int row = idx >> 8;          // i0*32+i1
    int col = idx & 255;         // a*16+q
    int i0 = row >> 5, i1 = row & 31;
    int a  = col >> 4, q  = col & 15;
    const float* p0 = c0 + a * 512 + i0 * 16;      // + b
    const float* p1 = c1 + i1 * 16 + q;            // + b*512
    float s = 0.f;
#pragma unroll
    for (int b = 0; b < 16; b++)
        s = fmaf(p0[b], p1[b * 512], s);
    g_T2[idx] = s;
}

// M23[q,o0,o1,a] = sum_d core2[q,o0,d] * core3[d,o1,a]
// stored as g_M23[(o0*64+o1)*256 + a*16+q]
// core2: (16,64,16) strides q:1024, o0:16, d:1
// core3: (16,64,16) strides d:1024, o1:16, a:1
__global__ void m23_kernel(const float* __restrict__ c2, const float* __restrict__ c3) {
    int idx = blockIdx.x * blockDim.x + threadIdx.x;   // 4096*256 threads
    int row = idx >> 8;          // o0*64+o1
    int col = idx & 255;         // a*16+q
    int o0 = row >> 6, o1 = row & 63;
    int a  = col >> 4, q  = col & 15;
    const float* p2 = c2 + q * 1024 + o0 * 16;     // + d
    const float* p3 = c3 + o1 * 16 + a;            // + d*1024
    float s = 0.f;
#pragma unroll
    for (int d = 0; d < 16; d++)
        s = fmaf(p2[d], p3[d * 1024], s);
    g_M23[idx] = s;
}

// ---------------------------------------------------------------------------
// C[M,N] = A[M,K] * B[N,K]^T (+ bias[N]).  All dims divisible by tile sizes.
#define BM 128
#define BN 128
#define BK 16
#define TM 8
#define TN 8

__global__ __launch_bounds__(256, 2)
void sgemm_nt(const float* __restrict__ A, const float* __restrict__ B,
              const float* __restrict__ bias, float* __restrict__ C,
              int M, int N, int K) {
    __shared__ float As[BK][BM];
    __shared__ float Bs[BK][BN];
    const int tid  = threadIdx.x;
    const int brow = blockIdx.y * BM;
    const int bcol = blockIdx.x * BN;
    const int tr = (tid >> 4) * TM;   // 0..120
    const int tc = (tid & 15) * TN;   // 0..120

    float acc[TM][TN] = {};
    float ra[TM], rb[TN];

    for (int kt = 0; kt < K; kt += BK) {
#pragma unroll
        for (int i = 0; i < 2; i++) {
            int li = tid + i * 256;          // 0..511
            int r  = li >> 2;                // row in tile (BK/4 = 4 vec4 per row)
            int cv = (li & 3) << 2;          // k offset within tile
            float4 va = *reinterpret_cast<const float4*>(
                A + (size_t)(brow + r) * K + kt + cv);
            As[cv + 0][r] = va.x; As[cv + 1][r] = va.y;
            As[cv + 2][r] = va.z; As[cv + 3][r] = va.w;
            float4 vb = *reinterpret_cast<const float4*>(
                B + (size_t)(bcol + r) * K + kt + cv);
            Bs[cv + 0][r] = vb.x; Bs[cv + 1][r] = vb.y;
            Bs[cv + 2][r] = vb.z; Bs[cv + 3][r] = vb.w;
        }
        __syncthreads();
#pragma unroll
        for (int k = 0; k < BK; k++) {
#pragma unroll
            for (int i = 0; i < TM; i++) ra[i] = As[k][tr + i];
#pragma unroll
            for (int j = 0; j < TN; j++) rb[j] = Bs[k][tc + j];
#pragma unroll
            for (int i = 0; i < TM; i++)
#pragma unroll
                for (int j = 0; j < TN; j++)
                    acc[i][j] = fmaf(ra[i], rb[j], acc[i][j]);
        }
        __syncthreads();
    }

    float bb[TN];
#pragma unroll
    for (int j = 0; j < TN; j++) bb[j] = bias ? bias[bcol + tc + j] : 0.f;

#pragma unroll
    for (int i = 0; i < TM; i++) {
        float* cp = C + (size_t)(brow + tr + i) * N + bcol + tc;
#pragma unroll
        for (int j = 0; j < TN; j += 4) {
            float4 v;
            v.x = acc[i][j + 0] + bb[j + 0];
            v.y = acc[i][j + 1] + bb[j + 1];
            v.z = acc[i][j + 2] + bb[j + 2];
            v.w = acc[i][j + 3] + bb[j + 3];
            *reinterpret_cast<float4*>(cp + j) = v;
        }
    }
}

// ---------------------------------------------------------------------------
extern "C" void kernel_launch(void* const* d_in, const int* in_sizes, int n_in,
                              void* d_out, int out_size) {
    (void)in_sizes; (void)n_in; (void)out_size;
    const float* x     = (const float*)d_in[0];   // (8192, 1024)
    const float* core0 = (const float*)d_in[1];   // (16,32,16)
    const float* core1 = (const float*)d_in[2];   // (16,32,16)
    const float* core2 = (const float*)d_in[3];   // (16,64,16)
    const float* core3 = (const float*)d_in[4];   // (16,64,16)
    const float* bias  = (const float*)d_in[5];   // (4096,)
    float* out = (float*)d_out;                   // (8192, 4096)

    float* T2;  cudaGetSymbolAddress((void**)&T2,  g_T2);
    float* M23; cudaGetSymbolAddress((void**)&M23, g_M23);
    float* W;   cudaGetSymbolAddress((void**)&W,   g_W);

    // 1) small core contractions
    t2_kernel <<<1024, 256>>>(core0, core1);
    m23_kernel<<<4096, 256>>>(core2, core3);

    // 2) W[1024,4096] = T2[1024,256] @ M23[4096,256]^T   (row-major == ref flat)
    {
        dim3 grid(N_OUT / BN, 1024 / BM);
        sgemm_nt<<<grid, 256>>>(T2, M23, nullptr, W, 1024, N_OUT, RQ);
    }

    // 3) out[8192,4096] = x[8192,1024] @ Wmat[4096,1024]^T + bias
    //    (W buffer reinterpreted as [4096][1024] — exactly the reference reshape)
    {
        dim3 grid(N_OUT / BN, M_X / BM);
        sgemm_nt<<<grid, 256>>>(x, W, bias, out, M_X, N_OUT, K_IN);
    }
}

// round 8
// speedup vs baseline: 1.4327x; 1.4327x over previous
#include <cuda_runtime.h>
#include <cuda_bf16.h>
#include <cstddef>

#define M_X   8192
#define K_IN  1024      // x columns = (o0_lo, o1) space
#define N_OUT 4096
#define RQ    256       // (a,q)
#define RQ4   1024      // (h, a, q)

// Scratch (device globals; allocation-free per harness rules)
__device__ float g_T2[1024 * RQ];        // [p = i0*32+i1][a*16+q]          (1 MB)
__device__ float g_M23t[RQ4 * K_IN];     // [h*256+a*16+q][o0lo*64+o1]      (4 MB)
__device__ float g_Z[M_X * RQ4];         // [m][h*256+aq]                   (32 MB)

// ---------------------------------------------------------------------------
// T2[p][aq] = sum_b core0[a,i0,b] * core1[b,i1,q]
// core0 (a,i0,b): strides 512,16,1   core1 (b,i1,q): strides 512,16,1
__global__ void t2_kernel(const float* __restrict__ c0, const float* __restrict__ c1) {
    int idx = blockIdx.x * blockDim.x + threadIdx.x;   // 1024*256
    int p  = idx >> 8;           // i0*32+i1
    int aq = idx & 255;          // a*16+q
    int i0 = p >> 5, i1 = p & 31;
    int a  = aq >> 4, q = aq & 15;
    const float* p0 = c0 + a * 512 + i0 * 16;      // + b
    const float* p1 = c1 + i1 * 16 + q;            // + b*512
    float s = 0.f;
#pragma unroll
    for (int b = 0; b < 16; b++)
        s = fmaf(p0[b], p1[b * 512], s);
    g_T2[idx] = s;
}

// M23t[h*256+a*16+q][k'] = sum_d core2[q, o0, d] * core3[d, o1, a]
//   with o0 = h*16 + (k'>>6), o1 = k'&63
// core2 (q,o0,d): strides 1024,16,1   core3 (d,o1,a): strides 1024,16,1
__global__ void m23t_kernel(const float* __restrict__ c2, const float* __restrict__ c3) {
    int idx = blockIdx.x * blockDim.x + threadIdx.x;   // 1024*1024
    int np = idx >> 10;          // h*256 + a*16 + q
    int kp = idx & 1023;         // o0lo*64 + o1
    int h  = np >> 8, a = (np >> 4) & 15, q = np & 15;
    int o0 = h * 16 + (kp >> 6);
    int o1 = kp & 63;
    const float* p2 = c2 + q * 1024 + o0 * 16;     // + d
    const float* p3 = c3 + o1 * 16 + a;            // + d*1024
    float s = 0.f;
#pragma unroll
    for (int d = 0; d < 16; d++)
        s = fmaf(p2[d], p3[d * 1024], s);
    g_M23t[idx] = s;
}

// ---------------------------------------------------------------------------
// C[m][n] = sum_k A[m*lda+k] * B[n*ldb+k]  (+ bias), double-buffered smem.
// C element (m,n) stored at C[m*ldc + n*cstride]; bias[n*bstride].
#define BM 128
#define BN 128
#define BK 16
#define TM 8
#define TN 8

__global__ __launch_bounds__(256, 2)
void sgemm_nt(const float* __restrict__ A, int lda,
              const float* __restrict__ B, int ldb,
              const float* __restrict__ bias, int bstride,
              float* __restrict__ C, int ldc, int cstride,
              int K) {
    __shared__ float As[2][BK][BM];
    __shared__ float Bs[2][BK][BN];
    const int tid  = threadIdx.x;
    const int brow = blockIdx.y * BM;
    const int bcol = blockIdx.x * BN;
    const int tr = (tid >> 4) * TM;
    const int tc = (tid & 15) * TN;

    const int r0  = tid >> 2;                 // 0..63
    const int cv0 = (tid & 3) << 2;           // 0,4,8,12

    float acc[TM][TN] = {};

    // prologue: tile 0 -> buffer 0
#pragma unroll
    for (int i = 0; i < 2; i++) {
        int r = r0 + i * 64;
        float4 va = *reinterpret_cast<const float4*>(A + (size_t)(brow + r) * lda + cv0);
        As[0][cv0 + 0][r] = va.x; As[0][cv0 + 1][r] = va.y;
        As[0][cv0 + 2][r] = va.z; As[0][cv0 + 3][r] = va.w;
        float4 vb = *reinterpret_cast<const float4*>(B + (size_t)(bcol + r) * ldb + cv0);
        Bs[0][cv0 + 0][r] = vb.x; Bs[0][cv0 + 1][r] = vb.y;
        Bs[0][cv0 + 2][r] = vb.z; Bs[0][cv0 + 3][r] = vb.w;
    }
    __syncthreads();

    const int nk = K / BK;
    for (int t = 0; t < nk; t++) {
        const int buf = t & 1;
        if (t + 1 < nk) {
            const int kt = (t + 1) * BK;
#pragma unroll
            for (int i = 0; i < 2; i++) {
                int r = r0 + i * 64;
                float4 va = *reinterpret_cast<const float4*>(A + (size_t)(brow + r) * lda + kt + cv0);
                As[1 - buf][cv0 + 0][r] = va.x; As[1 - buf][cv0 + 1][r] = va.y;
                As[1 - buf][cv0 + 2][r] = va.z; As[1 - buf][cv0 + 3][r] = va.w;
                float4 vb = *reinterpret_cast<const float4*>(B + (size_t)(bcol + r) * ldb + kt + cv0);
                Bs[1 - buf][cv0 + 0][r] = vb.x; Bs[1 - buf][cv0 + 1][r] = vb.y;
                Bs[1 - buf][cv0 + 2][r] = vb.z; Bs[1 - buf][cv0 + 3][r] = vb.w;
            }
        }
#pragma unroll
        for (int k = 0; k < BK; k++) {
            float ra[TM], rb[TN];
#pragma unroll
            for (int i = 0; i < TM; i++) ra[i] = As[buf][k][tr + i];
#pragma unroll
            for (int j = 0; j < TN; j++) rb[j] = Bs[buf][k][tc + j];
#pragma unroll
            for (int i = 0; i < TM; i++)
#pragma unroll
                for (int j = 0; j < TN; j++)
                    acc[i][j] = fmaf(ra[i], rb[j], acc[i][j]);
        }
        __syncthreads();
    }

    float bb[TN];
#pragma unroll
    for (int j = 0; j < TN; j++)
        bb[j] = bias ? bias[(size_t)(bcol + tc + j) * bstride] : 0.f;

    if (cstride == 1) {
#pragma unroll
        for (int i = 0; i < TM; i++) {
            float* cp = C + (size_t)(brow + tr + i) * ldc + bcol + tc;
#pragma unroll
            for (int j = 0; j < TN; j += 4) {
                float4 v;
                v.x = acc[i][j + 0] + bb[j + 0];
                v.y = acc[i][j + 1] + bb[j + 1];
                v.z = acc[i][j + 2] + bb[j + 2];
                v.w = acc[i][j + 3] + bb[j + 3];
                *reinterpret_cast<float4*>(cp + j) = v;
            }
        }
    } else {
#pragma unroll
        for (int i = 0; i < TM; i++) {
            float* cp = C + (size_t)(brow + tr + i) * ldc + (size_t)(bcol + tc) * cstride;
#pragma unroll
            for (int j = 0; j < TN; j++)
                cp[(size_t)j * cstride] = acc[i][j] + bb[j];
        }
    }
}

// ---------------------------------------------------------------------------
extern "C" void kernel_launch(void* const* d_in, const int* in_sizes, int n_in,
                              void* d_out, int out_size) {
    (void)in_sizes; (void)n_in; (void)out_size;
    const float* x     = (const float*)d_in[0];   // (8192, 1024)
    const float* core0 = (const float*)d_in[1];   // (16,32,16)
    const float* core1 = (const float*)d_in[2];   // (16,32,16)
    const float* core2 = (const float*)d_in[3];   // (16,64,16)
    const float* core3 = (const float*)d_in[4];   // (16,64,16)
    const float* bias  = (const float*)d_in[5];   // (4096,)
    float* out = (float*)d_out;                   // (8192, 4096)

    float* T2;   cudaGetSymbolAddress((void**)&T2,   g_T2);
    float* M23t; cudaGetSymbolAddress((void**)&M23t, g_M23t);
    float* Z;    cudaGetSymbolAddress((void**)&Z,    g_Z);

    // 1) core contractions (tiny)
    t2_kernel  <<<1024, 256>>>(core0, core1);
    m23t_kernel<<<4096, 256>>>(core2, core3);

    // 2) Z[8192,1024] = x[8192,1024] @ M23t[1024,1024]^T          (17.2 GFLOP)
    {
        dim3 grid(RQ4 / BN, M_X / BM);
        sgemm_nt<<<grid, 256>>>(x, K_IN, M23t, K_IN,
                                nullptr, 1, Z, RQ4, 1, K_IN);
    }

    // 3) for h in 0..3: out[m][p*4+h] = Z[m][h*256+:] @ T2[p][:]^T + bias[p*4+h]
    //    4x (8192 x 1024 x 256) GEMMs                             (17.2 GFLOP)
    for (int h = 0; h < 4; h++) {
        dim3 grid(1024 / BN, M_X / BM);
        sgemm_nt<<<grid, 256>>>(Z + h * RQ, RQ4, T2, RQ,
                                bias + h, 4, out + h, N_OUT, 4, RQ);
    }
}

// round 11
// speedup vs baseline: 3.1311x; 2.1854x over previous
#include <cuda_runtime.h>
#include <cuda_bf16.h>
#include <cstdint>
#include <cstddef>

#define M_X   8192
#define K_IN  1024
#define RQ4   1024

// ---------------------------------------------------------------------------
// Scratch (device globals; allocation-free)
__device__ __nv_bfloat16 g_T2hi[1024 * 256];
__device__ __nv_bfloat16 g_T2lo[1024 * 256];
__device__ __nv_bfloat16 g_M23thi[RQ4 * K_IN];
__device__ __nv_bfloat16 g_M23tlo[RQ4 * K_IN];
__device__ __nv_bfloat16 g_Zhi[(size_t)M_X * RQ4];   // also viewed as [32768][256]
__device__ __nv_bfloat16 g_Zlo[(size_t)M_X * RQ4];

// ---------------------------------------------------------------------------
__device__ __forceinline__ uint32_t smem_u32(const void* p) {
    uint32_t a;
    asm("{ .reg .u64 t; cvta.to.shared.u64 t, %1; cvt.u32.u64 %0, t; }" : "=r"(a) : "l"(p));
    return a;
}
__device__ __forceinline__ void ldsm_x4(uint32_t r[4], uint32_t addr) {
    asm volatile("ldmatrix.sync.aligned.m8n8.x4.shared.b16 {%0,%1,%2,%3}, [%4];"
        : "=r"(r[0]), "=r"(r[1]), "=r"(r[2]), "=r"(r[3]) : "r"(addr));
}
__device__ __forceinline__ void mma16816(float c[4], const uint32_t a[4], const uint32_t b[2]) {
    asm volatile("mma.sync.aligned.m16n8k16.row.col.f32.bf16.bf16.f32 "
        "{%0,%1,%2,%3}, {%4,%5,%6,%7}, {%8,%9}, {%0,%1,%2,%3};"
        : "+f"(c[0]), "+f"(c[1]), "+f"(c[2]), "+f"(c[3])
        : "r"(a[0]), "r"(a[1]), "r"(a[2]), "r"(a[3]), "r"(b[0]), "r"(b[1]));
}
__device__ __forceinline__ uint32_t pk(__nv_bfloat16 a, __nv_bfloat16 b) {
    return (uint32_t)__bfloat16_as_ushort(a) | ((uint32_t)__bfloat16_as_ushort(b) << 16);
}

// smem layout: 80-byte row pitch (32 bf16 + pad) -> conflict-free ldmatrix
#define LDAB   80
#define SA_HI  0
#define SA_LO  10240
#define SB_HI  20480
#define SB_LO  30720
#define BUFSZ  40960
#define SMEMSZ (2 * BUFSZ)    // 81920 B

// ---------------------------------------------------------------------------
// prep: T2[p][aq] = sum_b core0[a,i0,b]*core1[b,i1,q]  -> bf16 hi/lo
__global__ void t2_split_kernel(const float* __restrict__ c0, const float* __restrict__ c1,
                                __nv_bfloat16* __restrict__ hi, __nv_bfloat16* __restrict__ lo) {
    int idx = blockIdx.x * blockDim.x + threadIdx.x;   // 1024*256
    int p  = idx >> 8, aq = idx & 255;
    int i0 = p >> 5, i1 = p & 31;
    int a  = aq >> 4, q = aq & 15;
    const float* p0 = c0 + a * 512 + i0 * 16;
    const float* p1 = c1 + i1 * 16 + q;
    float s = 0.f;
#pragma unroll
    for (int b = 0; b < 16; b++) s = fmaf(p0[b], p1[b * 512], s);
    __nv_bfloat16 h = __float2bfloat16(s);
    hi[idx] = h;
    lo[idx] = __float2bfloat16(s - __bfloat162float(h));
}

// prep: M23t[h*256+a*16+q][o0lo*64+o1] = sum_d core2[q,o0,d]*core3[d,o1,a] -> hi/lo
__global__ void m23t_split_kernel(const float* __restrict__ c2, const float* __restrict__ c3,
                                  __nv_bfloat16* __restrict__ hi, __nv_bfloat16* __restrict__ lo) {
    int idx = blockIdx.x * blockDim.x + threadIdx.x;   // 1024*1024
    int np = idx >> 10, kp = idx & 1023;
    int h = np >> 8, a = (np >> 4) & 15, q = np & 15;
    int o0 = h * 16 + (kp >> 6), o1 = kp & 63;
    const float* p2 = c2 + q * 1024 + o0 * 16;
    const float* p3 = c3 + o1 * 16 + a;
    float s = 0.f;
#pragma unroll
    for (int d = 0; d < 16; d++) s = fmaf(p2[d], p3[d * 1024], s);
    __nv_bfloat16 hh = __float2bfloat16(s);
    hi[idx] = hh;
    lo[idx] = __float2bfloat16(s - __bfloat162float(hh));
}

// ---------------------------------------------------------------------------
// shared compute core: one BK=32 tile, bf16x3, warp tile 32x64
__device__ __forceinline__ void compute_tile(uint32_t sb, uint32_t bufo,
                                             int m_w, int n_w, int lane,
                                             float acc[2][8][4]) {
    const int tile = lane >> 3, trow = lane & 7;
#pragma unroll
    for (int ks = 0; ks < 2; ks++) {
        uint32_t aH[2][4], aL[2][4];
#pragma unroll
        for (int mt = 0; mt < 2; mt++) {
            uint32_t off = (uint32_t)((m_w + mt * 16 + (tile & 1) * 8 + trow) * LDAB
                                      + ks * 32 + (tile >> 1) * 16);
            ldsm_x4(aH[mt], sb + bufo + SA_HI + off);
            ldsm_x4(aL[mt], sb + bufo + SA_LO + off);
        }
        uint32_t bH[8][2], bL[8][2];
#pragma unroll
        for (int np = 0; np < 4; np++) {
            // x4 tiles: (n0,k0),(n0,k8),(n8,k0),(n8,k8): n-half = tile>>1, k-half = tile&1
            uint32_t off = (uint32_t)((n_w + np * 16 + (tile >> 1) * 8 + trow) * LDAB
                                      + ks * 32 + (tile & 1) * 16);
            uint32_t t0[4], t1[4];
            ldsm_x4(t0, sb + bufo + SB_HI + off);
            bH[np * 2][0] = t0[0]; bH[np * 2][1] = t0[1];
            bH[np * 2 + 1][0] = t0[2]; bH[np * 2 + 1][1] = t0[3];
            ldsm_x4(t1, sb + bufo + SB_LO + off);
            bL[np * 2][0] = t1[0]; bL[np * 2][1] = t1[1];
            bL[np * 2 + 1][0] = t1[2]; bL[np * 2 + 1][1] = t1[3];
        }
#pragma unroll
        for (int mt = 0; mt < 2; mt++)
#pragma unroll
            for (int nt = 0; nt < 8; nt++) {
                mma16816(acc[mt][nt], aH[mt], bH[nt]);
                mma16816(acc[mt][nt], aH[mt], bL[nt]);
                mma16816(acc[mt][nt], aL[mt], bH[nt]);
            }
    }
}

// ---------------------------------------------------------------------------
// GEMM1: Z[8192,1024] = x(fp32) @ M23t^T, bf16x3; epilogue splits Z -> hi/lo.
__global__ __launch_bounds__(256, 1)
void gemm1_mma(const float* __restrict__ x,
               const __nv_bfloat16* __restrict__ Bh, const __nv_bfloat16* __restrict__ Bl,
               __nv_bfloat16* __restrict__ Zhi, __nv_bfloat16* __restrict__ Zlo) {
    extern __shared__ char smem[];
    const int tid = threadIdx.x, wid = tid >> 5, lane = tid & 31;
    const int m0 = blockIdx.y * 128, n0 = blockIdx.x * 128;
    const int m_w = (wid & 3) * 32, n_w = (wid >> 2) * 64;
    const uint32_t sb = smem_u32(smem);

    auto load_tile = [&](int t) {
        char* buf = smem + (t & 1) * BUFSZ;
        const int kt = t * 32;
        // A: x fp32 -> hi/lo bf16
#pragma unroll
        for (int i = 0; i < 4; i++) {
            int li = tid + i * 256;               // 0..1023
            int r = li >> 3, c4 = (li & 7) << 2;
            float4 v = *reinterpret_cast<const float4*>(x + (size_t)(m0 + r) * 1024 + kt + c4);
            __nv_bfloat16 h0 = __float2bfloat16(v.x), h1 = __float2bfloat16(v.y);
            __nv_bfloat16 h2 = __float2bfloat16(v.z), h3 = __float2bfloat16(v.w);
            __nv_bfloat16 l0 = __float2bfloat16(v.x - __bfloat162float(h0));
            __nv_bfloat16 l1 = __float2bfloat16(v.y - __bfloat162float(h1));
            __nv_bfloat16 l2 = __float2bfloat16(v.z - __bfloat162float(h2));
            __nv_bfloat16 l3 = __float2bfloat16(v.w - __bfloat162float(h3));
            *reinterpret_cast<uint2*>(buf + SA_HI + r * LDAB + c4 * 2) = make_uint2(pk(h0, h1), pk(h2, h3));
            *reinterpret_cast<uint2*>(buf + SA_LO + r * LDAB + c4 * 2) = make_uint2(pk(l0, l1), pk(l2, l3));
        }
        // B: bf16 hi/lo straight copy
#pragma unroll
        for (int i = 0; i < 2; i++) {
            int li = tid + i * 256;               // 0..511
            int rr = li >> 2, u = li & 3;
            size_t g = (size_t)(n0 + rr) * 1024 + kt + u * 8;
            *reinterpret_cast<uint4*>(buf + SB_HI + rr * LDAB + u * 16) = *reinterpret_cast<const uint4*>(Bh + g);
            *reinterpret_cast<uint4*>(buf + SB_LO + rr * LDAB + u * 16) = *reinterpret_cast<const uint4*>(Bl + g);
        }
    };

    float acc[2][8][4] = {};
    load_tile(0);
    __syncthreads();
    const int NT = K_IN / 32;
    for (int t = 0; t < NT; t++) {
        if (t + 1 < NT) load_tile(t + 1);
        compute_tile(sb, (uint32_t)((t & 1) * BUFSZ), m_w, n_w, lane, acc);
        __syncthreads();
    }

    // epilogue: split to Zhi/Zlo
    const int gid = lane >> 2, tig = lane & 3;
#pragma unroll
    for (int mt = 0; mt < 2; mt++)
#pragma unroll
        for (int nt = 0; nt < 8; nt++) {
            int col = n0 + n_w + nt * 8 + tig * 2;
#pragma unroll
            for (int half = 0; half < 2; half++) {
                int rowm = m0 + m_w + mt * 16 + gid + half * 8;
                float v0 = acc[mt][nt][half * 2 + 0], v1 = acc[mt][nt][half * 2 + 1];
                __nv_bfloat16 h0 = __float2bfloat16(v0), h1 = __float2bfloat16(v1);
                __nv_bfloat16 l0 = __float2bfloat16(v0 - __bfloat162float(h0));
                __nv_bfloat16 l1 = __float2bfloat16(v1 - __bfloat162float(h1));
                *reinterpret_cast<uint32_t*>(Zhi + (size_t)rowm * 1024 + col) = pk(h0, h1);
                *reinterpret_cast<uint32_t*>(Zlo + (size_t)rowm * 1024 + col) = pk(l0, l1);
            }
        }
}

// ---------------------------------------------------------------------------
// GEMM2: V[32768,1024] = Z2[32768,256] @ T2^T, where Z2 row = m*4+h.
// V[(m*4+h)][p] -> out[m][4p+h]: CTA tile (128 rows = 32 m x 4 h, 128 p)
// is a DENSE out block -> smem-staged, float4-coalesced epilogue with bias.
__global__ __launch_bounds__(256, 1)
void gemm2_mma(const __nv_bfloat16* __restrict__ Ah, const __nv_bfloat16* __restrict__ Al,
               const __nv_bfloat16* __restrict__ Bh, const __nv_bfloat16* __restrict__ Bl,
               const float* __restrict__ bias, float* __restrict__ out) {
    extern __shared__ char smem[];
    const int tid = threadIdx.x, wid = tid >> 5, lane = tid & 31;
    const int r20 = blockIdx.y * 128;     // Z2 row base (m*4+h)
    const int p0  = blockIdx.x * 128;
    const int m_w = (wid & 3) * 32, n_w = (wid >> 2) * 64;
    const uint32_t sb = smem_u32(smem);

    auto load_tile = [&](int t) {
        char* buf = smem + (t & 1) * BUFSZ;
        const int kt = t * 32;
#pragma unroll
        for (int i = 0; i < 2; i++) {
            int li = tid + i * 256;
            int rr = li >> 2, u = li & 3;
            size_t ga = (size_t)(r20 + rr) * 256 + kt + u * 8;
            *reinterpret_cast<uint4*>(buf + SA_HI + rr * LDAB + u * 16) = *reinterpret_cast<const uint4*>(Ah + ga);
            *reinterpret_cast<uint4*>(buf + SA_LO + rr * LDAB + u * 16) = *reinterpret_cast<const uint4*>(Al + ga);
            size_t gb = (size_t)(p0 + rr) * 256 + kt + u * 8;
            *reinterpret_cast<uint4*>(buf + SB_HI + rr * LDAB + u * 16) = *reinterpret_cast<const uint4*>(Bh + gb);
            *reinterpret_cast<uint4*>(buf + SB_LO + rr * LDAB + u * 16) = *reinterpret_cast<const uint4*>(Bl + gb);
        }
    };

    float acc[2][8][4] = {};
    load_tile(0);
    __syncthreads();
    const int NT = 256 / 32;
    for (int t = 0; t < NT; t++) {
        if (t + 1 < NT) load_tile(t + 1);
        compute_tile(sb, (uint32_t)((t & 1) * BUFSZ), m_w, n_w, lane, acc);
        __syncthreads();
    }

    // stage to smem [128][132] fp32 (reuses the 80KB buffers; 67.6KB needed)
    __syncthreads();
    float* Cs = reinterpret_cast<float*>(smem);
    const int gid = lane >> 2, tig = lane & 3;
#pragma unroll
    for (int mt = 0; mt < 2; mt++)
#pragma unroll
        for (int nt = 0; nt < 8; nt++) {
            int col = n_w + nt * 8 + tig * 2;
#pragma unroll
            for (int half = 0; half < 2; half++) {
                int r = m_w + mt * 16 + gid + half * 8;
                Cs[r * 132 + col]     = acc[mt][nt][half * 2 + 0];
                Cs[r * 132 + col + 1] = acc[mt][nt][half * 2 + 1];
            }
        }
    __syncthreads();

    // out[m][4p+h] = Cs[(mm*4+h)][p] + bias[4p+h], float4 over h
    const int mo0 = blockIdx.y * 32;
#pragma unroll
    for (int i = 0; i < 16; i++) {
        int li = tid + i * 256;               // 0..4095
        int p  = li & 127, mm = li >> 7;      // mm 0..31
        float4 b4 = *reinterpret_cast<const float4*>(bias + (size_t)(p0 + p) * 4);
        float4 v;
        v.x = Cs[(mm * 4 + 0) * 132 + p] + b4.x;
        v.y = Cs[(mm * 4 + 1) * 132 + p] + b4.y;
        v.z = Cs[(mm * 4 + 2) * 132 + p] + b4.z;
        v.w = Cs[(mm * 4 + 3) * 132 + p] + b4.w;
        *reinterpret_cast<float4*>(out + (size_t)(mo0 + mm) * 4096 + (size_t)(p0 + p) * 4) = v;
    }
}

// ---------------------------------------------------------------------------
extern "C" void kernel_launch(void* const* d_in, const int* in_sizes, int n_in,
                              void* d_out, int out_size) {
    (void)in_sizes; (void)n_in; (void)out_size;
    const float* x     = (const float*)d_in[0];
    const float* core0 = (const float*)d_in[1];
    const float* core1 = (const float*)d_in[2];
    const float* core2 = (const float*)d_in[3];
    const float* core3 = (const float*)d_in[4];
    const float* bias  = (const float*)d_in[5];
    float* out = (float*)d_out;

    __nv_bfloat16 *T2hi, *T2lo, *Mhi, *Mlo, *Zhi, *Zlo;
    cudaGetSymbolAddress((void**)&T2hi, g_T2hi);
    cudaGetSymbolAddress((void**)&T2lo, g_T2lo);
    cudaGetSymbolAddress((void**)&Mhi,  g_M23thi);
    cudaGetSymbolAddress((void**)&Mlo,  g_M23tlo);
    cudaGetSymbolAddress((void**)&Zhi,  g_Zhi);
    cudaGetSymbolAddress((void**)&Zlo,  g_Zlo);

    cudaFuncSetAttribute(gemm1_mma, cudaFuncAttributeMaxDynamicSharedMemorySize, SMEMSZ);
    cudaFuncSetAttribute(gemm2_mma, cudaFuncAttributeMaxDynamicSharedMemorySize, SMEMSZ);

    t2_split_kernel  <<<1024, 256>>>(core0, core1, T2hi, T2lo);
    m23t_split_kernel<<<4096, 256>>>(core2, core3, Mhi, Mlo);

    // GEMM1: Z = x @ M23t^T   grid (n-tiles 8, m-tiles 64)
    gemm1_mma<<<dim3(8, 64), 256, SMEMSZ>>>(x, Mhi, Mlo, Zhi, Zlo);

    // GEMM2: out = Z2 @ T2^T + bias   grid (p-tiles 8, row-tiles 256)
    gemm2_mma<<<dim3(8, 256), 256, SMEMSZ>>>(Zhi, Zlo, T2hi, T2lo, bias, out);
}

// round 12
// speedup vs baseline: 3.8471x; 1.2286x over previous
#include <cuda_runtime.h>
#include <cuda_bf16.h>
#include <cstdint>
#include <cstddef>

#define M_X   8192
#define K_IN  1024
#define RQ4   1024

// ---------------------------------------------------------------------------
// Scratch (device globals; allocation-free)
__device__ __nv_bfloat16 g_T2hi[1024 * 256];
__device__ __nv_bfloat16 g_T2lo[1024 * 256];
__device__ __nv_bfloat16 g_M23thi[RQ4 * K_IN];
__device__ __nv_bfloat16 g_M23tlo[RQ4 * K_IN];
__device__ __nv_bfloat16 g_Xhi[(size_t)M_X * K_IN];
__device__ __nv_bfloat16 g_Xlo[(size_t)M_X * K_IN];
__device__ __nv_bfloat16 g_Zhi[(size_t)M_X * RQ4];   // also viewed as [32768][256]
__device__ __nv_bfloat16 g_Zlo[(size_t)M_X * RQ4];

// ---------------------------------------------------------------------------
__device__ __forceinline__ uint32_t smem_u32(const void* p) {
    uint32_t a;
    asm("{ .reg .u64 t; cvta.to.shared.u64 t, %1; cvt.u32.u64 %0, t; }" : "=r"(a) : "l"(p));
    return a;
}
__device__ __forceinline__ void ldsm_x4(uint32_t r[4], uint32_t addr) {
    asm volatile("ldmatrix.sync.aligned.m8n8.x4.shared.b16 {%0,%1,%2,%3}, [%4];"
        : "=r"(r[0]), "=r"(r[1]), "=r"(r[2]), "=r"(r[3]) : "r"(addr));
}
__device__ __forceinline__ void mma16816(float c[4], const uint32_t a[4], const uint32_t b[2]) {
    asm volatile("mma.sync.aligned.m16n8k16.row.col.f32.bf16.bf16.f32 "
        "{%0,%1,%2,%3}, {%4,%5,%6,%7}, {%8,%9}, {%0,%1,%2,%3};"
        : "+f"(c[0]), "+f"(c[1]), "+f"(c[2]), "+f"(c[3])
        : "r"(a[0]), "r"(a[1]), "r"(a[2]), "r"(a[3]), "r"(b[0]), "r"(b[1]));
}
__device__ __forceinline__ uint32_t pk(__nv_bfloat16 a, __nv_bfloat16 b) {
    return (uint32_t)__bfloat16_as_ushort(a) | ((uint32_t)__bfloat16_as_ushort(b) << 16);
}
__device__ __forceinline__ void cp16(uint32_t sdst, const void* gsrc) {
    asm volatile("cp.async.cg.shared.global [%0], [%1], 16;" :: "r"(sdst), "l"(gsrc));
}
#define CP_COMMIT()  asm volatile("cp.async.commit_group;" ::: "memory")
#define CP_WAIT(n)   asm volatile("cp.async.wait_group %0;" :: "n"(n) : "memory")

// smem layout: 80-byte row pitch (32 bf16 + pad) -> conflict-free ldmatrix
#define LDAB   80
#define SA_HI  0
#define SA_LO  10240
#define SB_HI  20480
#define SB_LO  30720
#define BUFSZ  40960
#define SMEMSZ (2 * BUFSZ)    // 81920 B

// ---------------------------------------------------------------------------
// prep: x fp32 -> bf16 hi/lo  (8192x1024)
__global__ void x_split_kernel(const float* __restrict__ x,
                               __nv_bfloat16* __restrict__ hi, __nv_bfloat16* __restrict__ lo) {
    size_t idx = (size_t)blockIdx.x * blockDim.x + threadIdx.x;  // 2M threads, 4 elems each
    float4 v = reinterpret_cast<const float4*>(x)[idx];
    __nv_bfloat16 h0 = __float2bfloat16(v.x), h1 = __float2bfloat16(v.y);
    __nv_bfloat16 h2 = __float2bfloat16(v.z), h3 = __float2bfloat16(v.w);
    __nv_bfloat16 l0 = __float2bfloat16(v.x - __bfloat162float(h0));
    __nv_bfloat16 l1 = __float2bfloat16(v.y - __bfloat162float(h1));
    __nv_bfloat16 l2 = __float2bfloat16(v.z - __bfloat162float(h2));
    __nv_bfloat16 l3 = __float2bfloat16(v.w - __bfloat162float(h3));
    reinterpret_cast<uint2*>(hi)[idx] = make_uint2(pk(h0, h1), pk(h2, h3));
    reinterpret_cast<uint2*>(lo)[idx] = make_uint2(pk(l0, l1), pk(l2, l3));
}

// prep: T2[p][aq] = sum_b core0[a,i0,b]*core1[b,i1,q]  -> bf16 hi/lo
__global__ void t2_split_kernel(const float* __restrict__ c0, const float* __restrict__ c1,
                                __nv_bfloat16* __restrict__ hi, __nv_bfloat16* __restrict__ lo) {
    int idx = blockIdx.x * blockDim.x + threadIdx.x;   // 1024*256
    int p  = idx >> 8, aq = idx & 255;
    int i0 = p >> 5, i1 = p & 31;
    int a  = aq >> 4, q = aq & 15;
    const float* p0 = c0 + a * 512 + i0 * 16;
    const float* p1 = c1 + i1 * 16 + q;
    float s = 0.f;
#pragma unroll
    for (int b = 0; b < 16; b++) s = fmaf(p0[b], p1[b * 512], s);
    __nv_bfloat16 h = __float2bfloat16(s);
    hi[idx] = h;
    lo[idx] = __float2bfloat16(s - __bfloat162float(h));
}

// prep: M23t[h*256+a*16+q][o0lo*64+o1] = sum_d core2[q,o0,d]*core3[d,o1,a] -> hi/lo
__global__ void m23t_split_kernel(const float* __restrict__ c2, const float* __restrict__ c3,
                                  __nv_bfloat16* __restrict__ hi, __nv_bfloat16* __restrict__ lo) {
    int idx = blockIdx.x * blockDim.x + threadIdx.x;   // 1024*1024
    int np = idx >> 10, kp = idx & 1023;
    int h = np >> 8, a = (np >> 4) & 15, q = np & 15;
    int o0 = h * 16 + (kp >> 6), o1 = kp & 63;
    const float* p2 = c2 + q * 1024 + o0 * 16;
    const float* p3 = c3 + o1 * 16 + a;
    float s = 0.f;
#pragma unroll
    for (int d = 0; d < 16; d++) s = fmaf(p2[d], p3[d * 1024], s);
    __nv_bfloat16 hh = __float2bfloat16(s);
    hi[idx] = hh;
    lo[idx] = __float2bfloat16(s - __bfloat162float(hh));
}

// ---------------------------------------------------------------------------
// compute core: one BK=32 tile, bf16x3, warp tile 32x64.
// PASS-MAJOR ordering: 16 independent MMAs between reuses of any accumulator.
__device__ __forceinline__ void compute_tile(uint32_t sb, uint32_t bufo,
                                             int m_w, int n_w, int lane,
                                             float acc[2][8][4]) {
    const int tile = lane >> 3, trow = lane & 7;
#pragma unroll
    for (int ks = 0; ks < 2; ks++) {
        uint32_t aH[2][4], aL[2][4];
#pragma unroll
        for (int mt = 0; mt < 2; mt++) {
            uint32_t off = (uint32_t)((m_w + mt * 16 + (tile & 1) * 8 + trow) * LDAB
                                      + ks * 32 + (tile >> 1) * 16);
            ldsm_x4(aH[mt], sb + bufo + SA_HI + off);
            ldsm_x4(aL[mt], sb + bufo + SA_LO + off);
        }
        uint32_t bH[8][2], bL[8][2];
#pragma unroll
        for (int np = 0; np < 4; np++) {
            uint32_t off = (uint32_t)((n_w + np * 16 + (tile >> 1) * 8 + trow) * LDAB
                                      + ks * 32 + (tile & 1) * 16);
            uint32_t t0[4], t1[4];
            ldsm_x4(t0, sb + bufo + SB_HI + off);
            bH[np * 2][0] = t0[0]; bH[np * 2][1] = t0[1];
            bH[np * 2 + 1][0] = t0[2]; bH[np * 2 + 1][1] = t0[3];
            ldsm_x4(t1, sb + bufo + SB_LO + off);
            bL[np * 2][0] = t1[0]; bL[np * 2][1] = t1[1];
            bL[np * 2 + 1][0] = t1[2]; bL[np * 2 + 1][1] = t1[3];
        }
        // pass 1: A_hi * B_hi
#pragma unroll
        for (int mt = 0; mt < 2; mt++)
#pragma unroll
            for (int nt = 0; nt < 8; nt++) mma16816(acc[mt][nt], aH[mt], bH[nt]);
        // pass 2: A_hi * B_lo
#pragma unroll
        for (int mt = 0; mt < 2; mt++)
#pragma unroll
            for (int nt = 0; nt < 8; nt++) mma16816(acc[mt][nt], aH[mt], bL[nt]);
        // pass 3: A_lo * B_hi
#pragma unroll
        for (int mt = 0; mt < 2; mt++)
#pragma unroll
            for (int nt = 0; nt < 8; nt++) mma16816(acc[mt][nt], aL[mt], bH[nt]);
    }
}

// ---------------------------------------------------------------------------
// GEMM1: Z[8192,1024] = X(hi/lo) @ M23t^T, bf16x3; epilogue splits Z -> hi/lo.
__global__ __launch_bounds__(256, 1)
void gemm1_mma(const __nv_bfloat16* __restrict__ Xh, const __nv_bfloat16* __restrict__ Xl,
               const __nv_bfloat16* __restrict__ Bh, const __nv_bfloat16* __restrict__ Bl,
               __nv_bfloat16* __restrict__ Zhi, __nv_bfloat16* __restrict__ Zlo) {
    extern __shared__ char smem[];
    const int tid = threadIdx.x, wid = tid >> 5, lane = tid & 31;
    const int m0 = blockIdx.y * 128, n0 = blockIdx.x * 128;
    const int m_w = (wid & 3) * 32, n_w = (wid >> 2) * 64;
    const uint32_t sb = smem_u32(smem);

    const int rr = tid >> 2, u = tid & 3;    // 64 rows per pass, 4x16B per row
    auto load_tile = [&](int t) {
        const int kt = t * 32;
        uint32_t buf = sb + (t & 1) * BUFSZ;
#pragma unroll
        for (int i = 0; i < 2; i++) {
            int r = rr + i * 64;
            uint32_t so = (uint32_t)(r * LDAB + u * 16);
            size_t ga = (size_t)(m0 + r) * 1024 + kt + u * 8;
            cp16(buf + SA_HI + so, Xh + ga);
            cp16(buf + SA_LO + so, Xl + ga);
            size_t gb = (size_t)(n0 + r) * 1024 + kt + u * 8;
            cp16(buf + SB_HI + so, Bh + gb);
            cp16(buf + SB_LO + so, Bl + gb);
        }
    };

    float acc[2][8][4] = {};
    load_tile(0); CP_COMMIT();
    const int NT = K_IN / 32;
    for (int t = 0; t < NT; t++) {
        if (t + 1 < NT) { load_tile(t + 1); CP_COMMIT(); CP_WAIT(1); }
        else            { CP_WAIT(0); }
        __syncthreads();
        compute_tile(sb, (uint32_t)((t & 1) * BUFSZ), m_w, n_w, lane, acc);
        __syncthreads();
    }

    // epilogue: split to Zhi/Zlo
    const int gid = lane >> 2, tig = lane & 3;
#pragma unroll
    for (int mt = 0; mt < 2; mt++)
#pragma unroll
        for (int nt = 0; nt < 8; nt++) {
            int col = n0 + n_w + nt * 8 + tig * 2;
#pragma unroll
            for (int half = 0; half < 2; half++) {
                int rowm = m0 + m_w + mt * 16 + gid + half * 8;
                float v0 = acc[mt][nt][half * 2 + 0], v1 = acc[mt][nt][half * 2 + 1];
                __nv_bfloat16 h0 = __float2bfloat16(v0), h1 = __float2bfloat16(v1);
                __nv_bfloat16 l0 = __float2bfloat16(v0 - __bfloat162float(h0));
                __nv_bfloat16 l1 = __float2bfloat16(v1 - __bfloat162float(h1));
                *reinterpret_cast<uint32_t*>(Zhi + (size_t)rowm * 1024 + col) = pk(h0, h1);
                *reinterpret_cast<uint32_t*>(Zlo + (size_t)rowm * 1024 + col) = pk(l0, l1);
            }
        }
}

// ---------------------------------------------------------------------------
// GEMM2: V[32768,1024] = Z2[32768,256] @ T2^T, Z2 row = m*4+h.
// CTA tile (128 Z2-rows, 128 p) = dense out block; smem-staged coalesced epilogue.
__global__ __launch_bounds__(256, 1)
void gemm2_mma(const __nv_bfloat16* __restrict__ Ah, const __nv_bfloat16* __restrict__ Al,
               const __nv_bfloat16* __restrict__ Bh, const __nv_bfloat16* __restrict__ Bl,
               const float* __restrict__ bias, float* __restrict__ out) {
    extern __shared__ char smem[];
    const int tid = threadIdx.x, wid = tid >> 5, lane = tid & 31;
    const int r20 = blockIdx.y * 128;     // Z2 row base (m*4+h)
    const int p0  = blockIdx.x * 128;
    const int m_w = (wid & 3) * 32, n_w = (wid >> 2) * 64;
    const uint32_t sb = smem_u32(smem);

    const int rr = tid >> 2, u = tid & 3;
    auto load_tile = [&](int t) {
        const int kt = t * 32;
        uint32_t buf = sb + (t & 1) * BUFSZ;
#pragma unroll
        for (int i = 0; i < 2; i++) {
            int r = rr + i * 64;
            uint32_t so = (uint32_t)(r * LDAB + u * 16);
            size_t ga = (size_t)(r20 + r) * 256 + kt + u * 8;
            cp16(buf + SA_HI + so, Ah + ga);
            cp16(buf + SA_LO + so, Al + ga);
            size_t gb = (size_t)(p0 + r) * 256 + kt + u * 8;
            cp16(buf + SB_HI + so, Bh + gb);
            cp16(buf + SB_LO + so, Bl + gb);
        }
    };

    float acc[2][8][4] = {};
    load_tile(0); CP_COMMIT();
    const int NT = 256 / 32;
    for (int t = 0; t < NT; t++) {
        if (t + 1 < NT) { load_tile(t + 1); CP_COMMIT(); CP_WAIT(1); }
        else            { CP_WAIT(0); }
        __syncthreads();
        compute_tile(sb, (uint32_t)((t & 1) * BUFSZ), m_w, n_w, lane, acc);
        __syncthreads();
    }

    // stage to smem [128][132] fp32
    __syncthreads();
    float* Cs = reinterpret_cast<float*>(smem);
    const int gid = lane >> 2, tig = lane & 3;
#pragma unroll
    for (int mt = 0; mt < 2; mt++)
#pragma unroll
        for (int nt = 0; nt < 8; nt++) {
            int col = n_w + nt * 8 + tig * 2;
#pragma unroll
            for (int half = 0; half < 2; half++) {
                int r = m_w + mt * 16 + gid + half * 8;
                Cs[r * 132 + col]     = acc[mt][nt][half * 2 + 0];
                Cs[r * 132 + col + 1] = acc[mt][nt][half * 2 + 1];
            }
        }
    __syncthreads();

    // out[m][4p+h] = Cs[(mm*4+h)][p] + bias[4p+h], float4 over h
    const int mo0 = blockIdx.y * 32;
#pragma unroll
    for (int i = 0; i < 16; i++) {
        int li = tid + i * 256;               // 0..4095
        int p  = li & 127, mm = li >> 7;      // mm 0..31
        float4 b4 = *reinterpret_cast<const float4*>(bias + (size_t)(p0 + p) * 4);
        float4 v;
        v.x = Cs[(mm * 4 + 0) * 132 + p] + b4.x;
        v.y = Cs[(mm * 4 + 1) * 132 + p] + b4.y;
        v.z = Cs[(mm * 4 + 2) * 132 + p] + b4.z;
        v.w = Cs[(mm * 4 + 3) * 132 + p] + b4.w;
        *reinterpret_cast<float4*>(out + (size_t)(mo0 + mm) * 4096 + (size_t)(p0 + p) * 4) = v;
    }
}

// ---------------------------------------------------------------------------
extern "C" void kernel_launch(void* const* d_in, const int* in_sizes, int n_in,
                              void* d_out, int out_size) {
    (void)in_sizes; (void)n_in; (void)out_size;
    const float* x     = (const float*)d_in[0];
    const float* core0 = (const float*)d_in[1];
    const float* core1 = (const float*)d_in[2];
    const float* core2 = (const float*)d_in[3];
    const float* core3 = (const float*)d_in[4];
    const float* bias  = (const float*)d_in[5];
    float* out = (float*)d_out;

    __nv_bfloat16 *T2hi, *T2lo, *Mhi, *Mlo, *Xhi, *Xlo, *Zhi, *Zlo;
    cudaGetSymbolAddress((void**)&T2hi, g_T2hi);
    cudaGetSymbolAddress((void**)&T2lo, g_T2lo);
    cudaGetSymbolAddress((void**)&Mhi,  g_M23thi);
    cudaGetSymbolAddress((void**)&Mlo,  g_M23tlo);
    cudaGetSymbolAddress((void**)&Xhi,  g_Xhi);
    cudaGetSymbolAddress((void**)&Xlo,  g_Xlo);
    cudaGetSymbolAddress((void**)&Zhi,  g_Zhi);
    cudaGetSymbolAddress((void**)&Zlo,  g_Zlo);

    cudaFuncSetAttribute(gemm1_mma, cudaFuncAttributeMaxDynamicSharedMemorySize, SMEMSZ);
    cudaFuncSetAttribute(gemm2_mma, cudaFuncAttributeMaxDynamicSharedMemorySize, SMEMSZ);

    t2_split_kernel  <<<1024, 256>>>(core0, core1, T2hi, T2lo);
    m23t_split_kernel<<<4096, 256>>>(core2, core3, Mhi, Mlo);
    x_split_kernel   <<<8192, 256>>>(x, Xhi, Xlo);

    // GEMM1: Z = X @ M23t^T   grid (n-tiles 8, m-tiles 64)
    gemm1_mma<<<dim3(8, 64), 256, SMEMSZ>>>(Xhi, Xlo, Mhi, Mlo, Zhi, Zlo);

    // GEMM2: out = Z2 @ T2^T + bias   grid (p-tiles 8, row-tiles 256)
    gemm2_mma<<<dim3(8, 256), 256, SMEMSZ>>>(Zhi, Zlo, T2hi, T2lo, bias, out);
}

// round 14
// speedup vs baseline: 4.0927x; 1.0639x over previous
#include <cuda_runtime.h>
#include <cuda_bf16.h>
#include <cstdint>
#include <cstddef>

#define M_X   8192
#define K_IN  1024
#define RQ4   1024

// ---------------------------------------------------------------------------
// Scratch (device globals; allocation-free)
__device__ __nv_bfloat16 g_T2hi[1024 * 256];
__device__ __nv_bfloat16 g_T2lo[1024 * 256];
__device__ __nv_bfloat16 g_M23thi[RQ4 * K_IN];
__device__ __nv_bfloat16 g_M23tlo[RQ4 * K_IN];
__device__ __nv_bfloat16 g_Xhi[(size_t)M_X * K_IN];
__device__ __nv_bfloat16 g_Xlo[(size_t)M_X * K_IN];
__device__ __nv_bfloat16 g_Zhi[(size_t)M_X * RQ4];   // also viewed as [32768][256]
__device__ __nv_bfloat16 g_Zlo[(size_t)M_X * RQ4];

// ---------------------------------------------------------------------------
__device__ __forceinline__ uint32_t smem_u32(const void* p) {
    uint32_t a;
    asm("{ .reg .u64 t; cvta.to.shared.u64 t, %1; cvt.u32.u64 %0, t; }" : "=r"(a) : "l"(p));
    return a;
}
__device__ __forceinline__ void ldsm_x4(uint32_t r[4], uint32_t addr) {
    asm volatile("ldmatrix.sync.aligned.m8n8.x4.shared.b16 {%0,%1,%2,%3}, [%4];"
        : "=r"(r[0]), "=r"(r[1]), "=r"(r[2]), "=r"(r[3]) : "r"(addr));
}
__device__ __forceinline__ void mma16816(float c[4], const uint32_t a[4], const uint32_t b[2]) {
    asm volatile("mma.sync.aligned.m16n8k16.row.col.f32.bf16.bf16.f32 "
        "{%0,%1,%2,%3}, {%4,%5,%6,%7}, {%8,%9}, {%0,%1,%2,%3};"
        : "+f"(c[0]), "+f"(c[1]), "+f"(c[2]), "+f"(c[3])
        : "r"(a[0]), "r"(a[1]), "r"(a[2]), "r"(a[3]), "r"(b[0]), "r"(b[1]));
}
__device__ __forceinline__ uint32_t pk(__nv_bfloat16 a, __nv_bfloat16 b) {
    return (uint32_t)__bfloat16_as_ushort(a) | ((uint32_t)__bfloat16_as_ushort(b) << 16);
}
__device__ __forceinline__ void cp16(uint32_t sdst, const void* gsrc) {
    asm volatile("cp.async.cg.shared.global [%0], [%1], 16;" :: "r"(sdst), "l"(gsrc));
}
#define CP_COMMIT()  asm volatile("cp.async.commit_group;" ::: "memory")
#define CP_WAIT(n)   asm volatile("cp.async.wait_group %0;" :: "n"(n) : "memory")

// smem layout: 80-byte row pitch (32 bf16 + pad) -> conflict-free ldmatrix
#define LDAB   80
#define SA_HI  0
#define SA_LO  10240
#define SB_HI  20480
#define SB_LO  30720
#define BUFSZ  40960
#define SMEMSZ (2 * BUFSZ)    // 81920 B

// ---------------------------------------------------------------------------
// prep: x fp32 -> bf16 hi/lo  (8192x1024)
__global__ void x_split_kernel(const float* __restrict__ x,
                               __nv_bfloat16* __restrict__ hi, __nv_bfloat16* __restrict__ lo) {
    size_t idx = (size_t)blockIdx.x * blockDim.x + threadIdx.x;  // 2M threads, 4 elems each
    float4 v = reinterpret_cast<const float4*>(x)[idx];
    __nv_bfloat16 h0 = __float2bfloat16(v.x), h1 = __float2bfloat16(v.y);
    __nv_bfloat16 h2 = __float2bfloat16(v.z), h3 = __float2bfloat16(v.w);
    __nv_bfloat16 l0 = __float2bfloat16(v.x - __bfloat162float(h0));
    __nv_bfloat16 l1 = __float2bfloat16(v.y - __bfloat162float(h1));
    __nv_bfloat16 l2 = __float2bfloat16(v.z - __bfloat162float(h2));
    __nv_bfloat16 l3 = __float2bfloat16(v.w - __bfloat162float(h3));
    reinterpret_cast<uint2*>(hi)[idx] = make_uint2(pk(h0, h1), pk(h2, h3));
    reinterpret_cast<uint2*>(lo)[idx] = make_uint2(pk(l0, l1), pk(l2, l3));
}

// prep: T2[p][aq] = sum_b core0[a,i0,b]*core1[b,i1,q]  -> bf16 hi/lo
__global__ void t2_split_kernel(const float* __restrict__ c0, const float* __restrict__ c1,
                                __nv_bfloat16* __restrict__ hi, __nv_bfloat16* __restrict__ lo) {
    int idx = blockIdx.x * blockDim.x + threadIdx.x;   // 1024*256
    int p  = idx >> 8, aq = idx & 255;
    int i0 = p >> 5, i1 = p & 31;
    int a  = aq >> 4, q = aq & 15;
    const float* p0 = c0 + a * 512 + i0 * 16;
    const float* p1 = c1 + i1 * 16 + q;
    float s = 0.f;
#pragma unroll
    for (int b = 0; b < 16; b++) s = fmaf(p0[b], p1[b * 512], s);
    __nv_bfloat16 h = __float2bfloat16(s);
    hi[idx] = h;
    lo[idx] = __float2bfloat16(s - __bfloat162float(h));
}

// prep: M23t[h*256+a*16+q][o0lo*64+o1] = sum_d core2[q,o0,d]*core3[d,o1,a] -> hi/lo
__global__ void m23t_split_kernel(const float* __restrict__ c2, const float* __restrict__ c3,
                                  __nv_bfloat16* __restrict__ hi, __nv_bfloat16* __restrict__ lo) {
    int idx = blockIdx.x * blockDim.x + threadIdx.x;   // 1024*1024
    int np = idx >> 10, kp = idx & 1023;
    int h = np >> 8, a = (np >> 4) & 15, q = np & 15;
    int o0 = h * 16 + (kp >> 6), o1 = kp & 63;
    const float* p2 = c2 + q * 1024 + o0 * 16;
    const float* p3 = c3 + o1 * 16 + a;
    float s = 0.f;
#pragma unroll
    for (int d = 0; d < 16; d++) s = fmaf(p2[d], p3[d * 1024], s);
    __nv_bfloat16 hh = __float2bfloat16(s);
    hi[idx] = hh;
    lo[idx] = __float2bfloat16(s - __bfloat162float(hh));
}

// ---------------------------------------------------------------------------
// compute core: one BK=32 tile, bf16x3, warp tile 32x32 (16 warps, 4x4 grid).
// PASS-MAJOR ordering: 8 independent MMAs between reuses of any accumulator.
__device__ __forceinline__ void compute_tile(uint32_t sb, uint32_t bufo,
                                             int m_w, int n_w, int lane,
                                             float acc[2][4][4]) {
    const int tile = lane >> 3, trow = lane & 7;
#pragma unroll
    for (int ks = 0; ks < 2; ks++) {
        uint32_t aH[2][4], aL[2][4];
#pragma unroll
        for (int mt = 0; mt < 2; mt++) {
            uint32_t off = (uint32_t)((m_w + mt * 16 + (tile & 1) * 8 + trow) * LDAB
                                      + ks * 32 + (tile >> 1) * 16);
            ldsm_x4(aH[mt], sb + bufo + SA_HI + off);
            ldsm_x4(aL[mt], sb + bufo + SA_LO + off);
        }
        uint32_t bH[4][2], bL[4][2];
#pragma unroll
        for (int np = 0; np < 2; np++) {
            // x4 tiles: (n0,k0),(n0,k8),(n8,k0),(n8,k8): n-half = tile>>1, k-half = tile&1
            uint32_t off = (uint32_t)((n_w + np * 16 + (tile >> 1) * 8 + trow) * LDAB
                                      + ks * 32 + (tile & 1) * 16);
            uint32_t t0[4], t1[4];
            ldsm_x4(t0, sb + bufo + SB_HI + off);
            bH[np * 2][0] = t0[0]; bH[np * 2][1] = t0[1];
            bH[np * 2 + 1][0] = t0[2]; bH[np * 2 + 1][1] = t0[3];
            ldsm_x4(t1, sb + bufo + SB_LO + off);
            bL[np * 2][0] = t1[0]; bL[np * 2][1] = t1[1];
            bL[np * 2 + 1][0] = t1[2]; bL[np * 2 + 1][1] = t1[3];
        }
        // pass 1: A_hi * B_hi
#pragma unroll
        for (int mt = 0; mt < 2; mt++)
#pragma unroll
            for (int nt = 0; nt < 4; nt++) mma16816(acc[mt][nt], aH[mt], bH[nt]);
        // pass 2: A_hi * B_lo
#pragma unroll
        for (int mt = 0; mt < 2; mt++)
#pragma unroll
            for (int nt = 0; nt < 4; nt++) mma16816(acc[mt][nt], aH[mt], bL[nt]);
        // pass 3: A_lo * B_hi
#pragma unroll
        for (int mt = 0; mt < 2; mt++)
#pragma unroll
            for (int nt = 0; nt < 4; nt++) mma16816(acc[mt][nt], aL[mt], bH[nt]);
    }
}

// ---------------------------------------------------------------------------
// GEMM1: Z[8192,1024] = X(hi/lo) @ M23t^T, bf16x3; epilogue splits Z -> hi/lo.
__global__ __launch_bounds__(512, 1)
void gemm1_mma(const __nv_bfloat16* __restrict__ Xh, const __nv_bfloat16* __restrict__ Xl,
               const __nv_bfloat16* __restrict__ Bh, const __nv_bfloat16* __restrict__ Bl,
               __nv_bfloat16* __restrict__ Zhi, __nv_bfloat16* __restrict__ Zlo) {
    extern __shared__ char smem[];
    const int tid = threadIdx.x, wid = tid >> 5, lane = tid & 31;
    const int m0 = blockIdx.y * 128, n0 = blockIdx.x * 128;
    const int m_w = (wid & 3) * 32, n_w = (wid >> 2) * 32;
    const uint32_t sb = smem_u32(smem);

    const int rr = tid >> 2, u = tid & 3;    // 128 rows, 4x16B per row, 1 per thread
    auto load_tile = [&](int t) {
        const int kt = t * 32;
        uint32_t buf = sb + (t & 1) * BUFSZ;
        uint32_t so = (uint32_t)(rr * LDAB + u * 16);
        size_t ga = (size_t)(m0 + rr) * 1024 + kt + u * 8;
        cp16(buf + SA_HI + so, Xh + ga);
        cp16(buf + SA_LO + so, Xl + ga);
        size_t gb = (size_t)(n0 + rr) * 1024 + kt + u * 8;
        cp16(buf + SB_HI + so, Bh + gb);
        cp16(buf + SB_LO + so, Bl + gb);
    };

    float acc[2][4][4] = {};
    load_tile(0); CP_COMMIT();
    const int NT = K_IN / 32;
    for (int t = 0; t < NT; t++) {
        if (t + 1 < NT) { load_tile(t + 1); CP_COMMIT(); CP_WAIT(1); }
        else            { CP_WAIT(0); }
        __syncthreads();
        compute_tile(sb, (uint32_t)((t & 1) * BUFSZ), m_w, n_w, lane, acc);
        __syncthreads();
    }

    // epilogue: split to Zhi/Zlo
    const int gid = lane >> 2, tig = lane & 3;
#pragma unroll
    for (int mt = 0; mt < 2; mt++)
#pragma unroll
        for (int nt = 0; nt < 4; nt++) {
            int col = n0 + n_w + nt * 8 + tig * 2;
#pragma unroll
            for (int half = 0; half < 2; half++) {
                int rowm = m0 + m_w + mt * 16 + gid + half * 8;
                float v0 = acc[mt][nt][half * 2 + 0], v1 = acc[mt][nt][half * 2 + 1];
                __nv_bfloat16 h0 = __float2bfloat16(v0), h1 = __float2bfloat16(v1);
                __nv_bfloat16 l0 = __float2bfloat16(v0 - __bfloat162float(h0));
                __nv_bfloat16 l1 = __float2bfloat16(v1 - __bfloat162float(h1));
                *reinterpret_cast<uint32_t*>(Zhi + (size_t)rowm * 1024 + col) = pk(h0, h1);
                *reinterpret_cast<uint32_t*>(Zlo + (size_t)rowm * 1024 + col) = pk(l0, l1);
            }
        }
}

// ---------------------------------------------------------------------------
// GEMM2: V[32768,1024] = Z2[32768,256] @ T2^T, Z2 row = m*4+h.
// CTA tile (128 Z2-rows, 128 p) = dense out block; smem-staged coalesced epilogue.
__global__ __launch_bounds__(512, 1)
void gemm2_mma(const __nv_bfloat16* __restrict__ Ah, const __nv_bfloat16* __restrict__ Al,
               const __nv_bfloat16* __restrict__ Bh, const __nv_bfloat16* __restrict__ Bl,
               const float* __restrict__ bias, float* __restrict__ out) {
    extern __shared__ char smem[];
    const int tid = threadIdx.x, wid = tid >> 5, lane = tid & 31;
    const int r20 = blockIdx.y * 128;     // Z2 row base (m*4+h)
    const int p0  = blockIdx.x * 128;
    const int m_w = (wid & 3) * 32, n_w = (wid >> 2) * 32;
    const uint32_t sb = smem_u32(smem);

    const int rr = tid >> 2, u = tid & 3;
    auto load_tile = [&](int t) {
        const int kt = t * 32;
        uint32_t buf = sb + (t & 1) * BUFSZ;
        uint32_t so = (uint32_t)(rr * LDAB + u * 16);
        size_t ga = (size_t)(r20 + rr) * 256 + kt + u * 8;
        cp16(buf + SA_HI + so, Ah + ga);
        cp16(buf + SA_LO + so, Al + ga);
        size_t gb = (size_t)(p0 + rr) * 256 + kt + u * 8;
        cp16(buf + SB_HI + so, Bh + gb);
        cp16(buf + SB_LO + so, Bl + gb);
    };

    float acc[2][4][4] = {};
    load_tile(0); CP_COMMIT();
    const int NT = 256 / 32;
    for (int t = 0; t < NT; t++) {
        if (t + 1 < NT) { load_tile(t + 1); CP_COMMIT(); CP_WAIT(1); }
        else            { CP_WAIT(0); }
        __syncthreads();
        compute_tile(sb, (uint32_t)((t & 1) * BUFSZ), m_w, n_w, lane, acc);
        __syncthreads();
    }

    // stage to smem [128][132] fp32
    __syncthreads();
    float* Cs = reinterpret_cast<float*>(smem);
    const int gid = lane >> 2, tig = lane & 3;
#pragma unroll
    for (int mt = 0; mt < 2; mt++)
#pragma unroll
        for (int nt = 0; nt < 4; nt++) {
            int col = n_w + nt * 8 + tig * 2;
#pragma unroll
            for (int half = 0; half < 2; half++) {
                int r = m_w + mt * 16 + gid + half * 8;
                Cs[r * 132 + col]     = acc[mt][nt][half * 2 + 0];
                Cs[r * 132 + col + 1] = acc[mt][nt][half * 2 + 1];
            }
        }
    __syncthreads();

    // out[m][4p+h] = Cs[(mm*4+h)][p] + bias[4p+h], float4 over h
    const int mo0 = blockIdx.y * 32;
#pragma unroll
    for (int i = 0; i < 8; i++) {
        int li = tid + i * 512;               // 0..4095
        int p  = li & 127, mm = li >> 7;      // mm 0..31
        float4 b4 = *reinterpret_cast<const float4*>(bias + (size_t)(p0 + p) * 4);
        float4 v;
        v.x = Cs[(mm * 4 + 0) * 132 + p] + b4.x;
        v.y = Cs[(mm * 4 + 1) * 132 + p] + b4.y;
        v.z = Cs[(mm * 4 + 2) * 132 + p] + b4.z;
        v.w = Cs[(mm * 4 + 3) * 132 + p] + b4.w;
        *reinterpret_cast<float4*>(out + (size_t)(mo0 + mm) * 4096 + (size_t)(p0 + p) * 4) = v;
    }
}

// ---------------------------------------------------------------------------
extern "C" void kernel_launch(void* const* d_in, const int* in_sizes, int n_in,
                              void* d_out, int out_size) {
    (void)in_sizes; (void)n_in; (void)out_size;
    const float* x     = (const float*)d_in[0];
    const float* core0 = (const float*)d_in[1];
    const float* core1 = (const float*)d_in[2];
    const float* core2 = (const float*)d_in[3];
    const float* core3 = (const float*)d_in[4];
    const float* bias  = (const float*)d_in[5];
    float* out = (float*)d_out;

    __nv_bfloat16 *T2hi, *T2lo, *Mhi, *Mlo, *Xhi, *Xlo, *Zhi, *Zlo;
    cudaGetSymbolAddress((void**)&T2hi, g_T2hi);
    cudaGetSymbolAddress((void**)&T2lo, g_T2lo);
    cudaGetSymbolAddress((void**)&Mhi,  g_M23thi);
    cudaGetSymbolAddress((void**)&Mlo,  g_M23tlo);
    cudaGetSymbolAddress((void**)&Xhi,  g_Xhi);
    cudaGetSymbolAddress((void**)&Xlo,  g_Xlo);
    cudaGetSymbolAddress((void**)&Zhi,  g_Zhi);
    cudaGetSymbolAddress((void**)&Zlo,  g_Zlo);

    cudaFuncSetAttribute(gemm1_mma, cudaFuncAttributeMaxDynamicSharedMemorySize, SMEMSZ);
    cudaFuncSetAttribute(gemm2_mma, cudaFuncAttributeMaxDynamicSharedMemorySize, SMEMSZ);

    t2_split_kernel  <<<1024, 256>>>(core0, core1, T2hi, T2lo);
    m23t_split_kernel<<<4096, 256>>>(core2, core3, Mhi, Mlo);
    x_split_kernel   <<<8192, 256>>>(x, Xhi, Xlo);

    // GEMM1: Z = X @ M23t^T   grid (n-tiles 8, m-tiles 64)
    gemm1_mma<<<dim3(8, 64), 512, SMEMSZ>>>(Xhi, Xlo, Mhi, Mlo, Zhi, Zlo);

    // GEMM2: out = Z2 @ T2^T + bias   grid (p-tiles 8, row-tiles 256)
    gemm2_mma<<<dim3(8, 256), 512, SMEMSZ>>>(Zhi, Zlo, T2hi, T2lo, bias, out);
}

// round 15
// speedup vs baseline: 4.2347x; 1.0347x over previous
#include <cuda_runtime.h>
#include <cuda_bf16.h>
#include <cstdint>
#include <cstddef>

#define M_X   8192
#define K_IN  1024
#define RQ4   1024

// ---------------------------------------------------------------------------
// Scratch (device globals; allocation-free)
__device__ __nv_bfloat16 g_T2hi[1024 * 256];
__device__ __nv_bfloat16 g_T2lo[1024 * 256];
__device__ __nv_bfloat16 g_M23thi[RQ4 * K_IN];
__device__ __nv_bfloat16 g_M23tlo[RQ4 * K_IN];
__device__ __nv_bfloat16 g_Xhi[(size_t)M_X * K_IN];
__device__ __nv_bfloat16 g_Xlo[(size_t)M_X * K_IN];
__device__ __nv_bfloat16 g_Zhi[(size_t)M_X * RQ4];   // also viewed as [32768][256]
__device__ __nv_bfloat16 g_Zlo[(size_t)M_X * RQ4];

// ---------------------------------------------------------------------------
__device__ __forceinline__ uint32_t smem_u32(const void* p) {
    uint32_t a;
    asm("{ .reg .u64 t; cvta.to.shared.u64 t, %1; cvt.u32.u64 %0, t; }" : "=r"(a) : "l"(p));
    return a;
}
__device__ __forceinline__ void ldsm_x4(uint32_t r[4], uint32_t addr) {
    asm volatile("ldmatrix.sync.aligned.m8n8.x4.shared.b16 {%0,%1,%2,%3}, [%4];"
        : "=r"(r[0]), "=r"(r[1]), "=r"(r[2]), "=r"(r[3]) : "r"(addr));
}
__device__ __forceinline__ void mma16816(float c[4], const uint32_t a[4], const uint32_t b[2]) {
    asm volatile("mma.sync.aligned.m16n8k16.row.col.f32.bf16.bf16.f32 "
        "{%0,%1,%2,%3}, {%4,%5,%6,%7}, {%8,%9}, {%0,%1,%2,%3};"
        : "+f"(c[0]), "+f"(c[1]), "+f"(c[2]), "+f"(c[3])
        : "r"(a[0]), "r"(a[1]), "r"(a[2]), "r"(a[3]), "r"(b[0]), "r"(b[1]));
}
__device__ __forceinline__ uint32_t pk(__nv_bfloat16 a, __nv_bfloat16 b) {
    return (uint32_t)__bfloat16_as_ushort(a) | ((uint32_t)__bfloat16_as_ushort(b) << 16);
}
__device__ __forceinline__ void cp16(uint32_t sdst, const void* gsrc) {
    asm volatile("cp.async.cg.shared.global [%0], [%1], 16;" :: "r"(sdst), "l"(gsrc));
}
#define CP_COMMIT()  asm volatile("cp.async.commit_group;" ::: "memory")
#define CP_WAIT(n)   asm volatile("cp.async.wait_group %0;" :: "n"(n) : "memory")

// smem: BK=64 -> 128B data + 16B pad per row (conflict-free ldmatrix: 4r mod 32 distinct)
#define LDAB   144
#define SA_HI  0
#define SA_LO  18432
#define SB_HI  36864
#define SB_LO  55296
#define STAGE  73728
#define NSTG   3
#define SMEMSZ (NSTG * STAGE)   // 221184 B

// ---------------------------------------------------------------------------
// prep: x fp32 -> bf16 hi/lo  (8192x1024)
__global__ void x_split_kernel(const float* __restrict__ x,
                               __nv_bfloat16* __restrict__ hi, __nv_bfloat16* __restrict__ lo) {
    size_t idx = (size_t)blockIdx.x * blockDim.x + threadIdx.x;
    float4 v = reinterpret_cast<const float4*>(x)[idx];
    __nv_bfloat16 h0 = __float2bfloat16(v.x), h1 = __float2bfloat16(v.y);
    __nv_bfloat16 h2 = __float2bfloat16(v.z), h3 = __float2bfloat16(v.w);
    __nv_bfloat16 l0 = __float2bfloat16(v.x - __bfloat162float(h0));
    __nv_bfloat16 l1 = __float2bfloat16(v.y - __bfloat162float(h1));
    __nv_bfloat16 l2 = __float2bfloat16(v.z - __bfloat162float(h2));
    __nv_bfloat16 l3 = __float2bfloat16(v.w - __bfloat162float(h3));
    reinterpret_cast<uint2*>(hi)[idx] = make_uint2(pk(h0, h1), pk(h2, h3));
    reinterpret_cast<uint2*>(lo)[idx] = make_uint2(pk(l0, l1), pk(l2, l3));
}

// prep: T2[p][aq] = sum_b core0[a,i0,b]*core1[b,i1,q]  -> bf16 hi/lo
__global__ void t2_split_kernel(const float* __restrict__ c0, const float* __restrict__ c1,
                                __nv_bfloat16* __restrict__ hi, __nv_bfloat16* __restrict__ lo) {
    int idx = blockIdx.x * blockDim.x + threadIdx.x;
    int p  = idx >> 8, aq = idx & 255;
    int i0 = p >> 5, i1 = p & 31;
    int a  = aq >> 4, q = aq & 15;
    const float* p0 = c0 + a * 512 + i0 * 16;
    const float* p1 = c1 + i1 * 16 + q;
    float s = 0.f;
#pragma unroll
    for (int b = 0; b < 16; b++) s = fmaf(p0[b], p1[b * 512], s);
    __nv_bfloat16 h = __float2bfloat16(s);
    hi[idx] = h;
    lo[idx] = __float2bfloat16(s - __bfloat162float(h));
}

// prep: M23t[h*256+a*16+q][o0lo*64+o1] = sum_d core2[q,o0,d]*core3[d,o1,a] -> hi/lo
__global__ void m23t_split_kernel(const float* __restrict__ c2, const float* __restrict__ c3,
                                  __nv_bfloat16* __restrict__ hi, __nv_bfloat16* __restrict__ lo) {
    int idx = blockIdx.x * blockDim.x + threadIdx.x;
    int np = idx >> 10, kp = idx & 1023;
    int h = np >> 8, a = (np >> 4) & 15, q = np & 15;
    int o0 = h * 16 + (kp >> 6), o1 = kp & 63;
    const float* p2 = c2 + q * 1024 + o0 * 16;
    const float* p3 = c3 + o1 * 16 + a;
    float s = 0.f;
#pragma unroll
    for (int d = 0; d < 16; d++) s = fmaf(p2[d], p3[d * 1024], s);
    __nv_bfloat16 hh = __float2bfloat16(s);
    hi[idx] = hh;
    lo[idx] = __float2bfloat16(s - __bfloat162float(hh));
}

// ---------------------------------------------------------------------------
// compute core: one BK=64 tile, bf16x3, warp tile 32x32 (16 warps, 4x4 grid).
// PASS-MAJOR ordering: 8 independent MMAs between reuses of any accumulator.
__device__ __forceinline__ void compute_tile(uint32_t sb, uint32_t bufo,
                                             int m_w, int n_w, int lane,
                                             float acc[2][4][4]) {
    const int tile = lane >> 3, trow = lane & 7;
#pragma unroll
    for (int ks = 0; ks < 4; ks++) {
        uint32_t aH[2][4], aL[2][4];
#pragma unroll
        for (int mt = 0; mt < 2; mt++) {
            uint32_t off = (uint32_t)((m_w + mt * 16 + (tile & 1) * 8 + trow) * LDAB
                                      + ks * 32 + (tile >> 1) * 16);
            ldsm_x4(aH[mt], sb + bufo + SA_HI + off);
            ldsm_x4(aL[mt], sb + bufo + SA_LO + off);
        }
        uint32_t bH[4][2], bL[4][2];
#pragma unroll
        for (int np = 0; np < 2; np++) {
            uint32_t off = (uint32_t)((n_w + np * 16 + (tile >> 1) * 8 + trow) * LDAB
                                      + ks * 32 + (tile & 1) * 16);
            uint32_t t0[4], t1[4];
            ldsm_x4(t0, sb + bufo + SB_HI + off);
            bH[np * 2][0] = t0[0]; bH[np * 2][1] = t0[1];
            bH[np * 2 + 1][0] = t0[2]; bH[np * 2 + 1][1] = t0[3];
            ldsm_x4(t1, sb + bufo + SB_LO + off);
            bL[np * 2][0] = t1[0]; bL[np * 2][1] = t1[1];
            bL[np * 2 + 1][0] = t1[2]; bL[np * 2 + 1][1] = t1[3];
        }
#pragma unroll
        for (int mt = 0; mt < 2; mt++)
#pragma unroll
            for (int nt = 0; nt < 4; nt++) mma16816(acc[mt][nt], aH[mt], bH[nt]);
#pragma unroll
        for (int mt = 0; mt < 2; mt++)
#pragma unroll
            for (int nt = 0; nt < 4; nt++) mma16816(acc[mt][nt], aH[mt], bL[nt]);
#pragma unroll
        for (int mt = 0; mt < 2; mt++)
#pragma unroll
            for (int nt = 0; nt < 4; nt++) mma16816(acc[mt][nt], aL[mt], bH[nt]);
    }
}

// ---------------------------------------------------------------------------
// GEMM1: Z[8192,1024] = X(hi/lo) @ M23t^T, bf16x3; epilogue splits Z -> hi/lo.
// 3-stage cp.async pipeline, BK=64, ONE syncthreads per tile.
__global__ __launch_bounds__(512, 1)
void gemm1_mma(const __nv_bfloat16* __restrict__ Xh, const __nv_bfloat16* __restrict__ Xl,
               const __nv_bfloat16* __restrict__ Bh, const __nv_bfloat16* __restrict__ Bl,
               __nv_bfloat16* __restrict__ Zhi, __nv_bfloat16* __restrict__ Zlo) {
    extern __shared__ char smem[];
    const int tid = threadIdx.x, wid = tid >> 5, lane = tid & 31;
    const int m0 = blockIdx.y * 128, n0 = blockIdx.x * 128;
    const int m_w = (wid & 3) * 32, n_w = (wid >> 2) * 32;
    const uint32_t sb = smem_u32(smem);

    const int u = tid & 7, rr = tid >> 3;   // chunk 0..7, row 0..63 (+64)
    auto load_tile = [&](int t, int slot) {
        const int kt = t * 64;
        uint32_t buf = sb + (uint32_t)slot * STAGE;
#pragma unroll
        for (int i = 0; i < 2; i++) {
            int r = rr + i * 64;
            uint32_t so = (uint32_t)(r * LDAB + u * 16);
            size_t ga = (size_t)(m0 + r) * 1024 + kt + u * 8;
            cp16(buf + SA_HI + so, Xh + ga);
            cp16(buf + SA_LO + so, Xl + ga);
            size_t gb = (size_t)(n0 + r) * 1024 + kt + u * 8;
            cp16(buf + SB_HI + so, Bh + gb);
            cp16(buf + SB_LO + so, Bl + gb);
        }
    };

    float acc[2][4][4] = {};
    load_tile(0, 0); CP_COMMIT();
    load_tile(1, 1); CP_COMMIT();

    const int NT = K_IN / 64;    // 16
    int sc = 0, sw = 2;          // compute slot, write slot
    for (int t = 0; t < NT; t++) {
        CP_WAIT(1);              // stage t landed (group t done, t+1 may be in flight)
        __syncthreads();         // all warps past compute(t-1) -> slot sw is free
        if (t + 2 < NT) load_tile(t + 2, sw);
        CP_COMMIT();             // always commit (empty groups keep wait(1) aligned)
        compute_tile(sb, (uint32_t)sc * STAGE, m_w, n_w, lane, acc);
        sc = (sc == NSTG - 1) ? 0 : sc + 1;
        sw = (sw == NSTG - 1) ? 0 : sw + 1;
    }

    // epilogue: split to Zhi/Zlo
    const int gid = lane >> 2, tig = lane & 3;
#pragma unroll
    for (int mt = 0; mt < 2; mt++)
#pragma unroll
        for (int nt = 0; nt < 4; nt++) {
            int col = n0 + n_w + nt * 8 + tig * 2;
#pragma unroll
            for (int half = 0; half < 2; half++) {
                int rowm = m0 + m_w + mt * 16 + gid + half * 8;
                float v0 = acc[mt][nt][half * 2 + 0], v1 = acc[mt][nt][half * 2 + 1];
                __nv_bfloat16 h0 = __float2bfloat16(v0), h1 = __float2bfloat16(v1);
                __nv_bfloat16 l0 = __float2bfloat16(v0 - __bfloat162float(h0));
                __nv_bfloat16 l1 = __float2bfloat16(v1 - __bfloat162float(h1));
                *reinterpret_cast<uint32_t*>(Zhi + (size_t)rowm * 1024 + col) = pk(h0, h1);
                *reinterpret_cast<uint32_t*>(Zlo + (size_t)rowm * 1024 + col) = pk(l0, l1);
            }
        }
}

// ---------------------------------------------------------------------------
// GEMM2: V[32768,1024] = Z2[32768,256] @ T2^T, Z2 row = m*4+h.
// CTA tile (128 Z2-rows, 128 p) = dense out block; smem-staged coalesced epilogue.
__global__ __launch_bounds__(512, 1)
void gemm2_mma(const __nv_bfloat16* __restrict__ Ah, const __nv_bfloat16* __restrict__ Al,
               const __nv_bfloat16* __restrict__ Bh, const __nv_bfloat16* __restrict__ Bl,
               const float* __restrict__ bias, float* __restrict__ out) {
    extern __shared__ char smem[];
    const int tid = threadIdx.x, wid = tid >> 5, lane = tid & 31;
    const int r20 = blockIdx.y * 128;     // Z2 row base (m*4+h)
    const int p0  = blockIdx.x * 128;
    const int m_w = (wid & 3) * 32, n_w = (wid >> 2) * 32;
    const uint32_t sb = smem_u32(smem);

    const int u = tid & 7, rr = tid >> 3;
    auto load_tile = [&](int t, int slot) {
        const int kt = t * 64;
        uint32_t buf = sb + (uint32_t)slot * STAGE;
#pragma unroll
        for (int i = 0; i < 2; i++) {
            int r = rr + i * 64;
            uint32_t so = (uint32_t)(r * LDAB + u * 16);
            size_t ga = (size_t)(r20 + r) * 256 + kt + u * 8;
            cp16(buf + SA_HI + so, Ah + ga);
            cp16(buf + SA_LO + so, Al + ga);
            size_t gb = (size_t)(p0 + r) * 256 + kt + u * 8;
            cp16(buf + SB_HI + so, Bh + gb);
            cp16(buf + SB_LO + so, Bl + gb);
        }
    };

    float acc[2][4][4] = {};
    load_tile(0, 0); CP_COMMIT();
    load_tile(1, 1); CP_COMMIT();

    const int NT = 256 / 64;     // 4
    int sc = 0, sw = 2;
    for (int t = 0; t < NT; t++) {
        CP_WAIT(1);
        __syncthreads();
        if (t + 2 < NT) load_tile(t + 2, sw);
        CP_COMMIT();
        compute_tile(sb, (uint32_t)sc * STAGE, m_w, n_w, lane, acc);
        sc = (sc == NSTG - 1) ? 0 : sc + 1;
        sw = (sw == NSTG - 1) ? 0 : sw + 1;
    }

    // stage to smem [128][132] fp32 (67.6 KB, fits in the 216 KB buffer)
    __syncthreads();
    float* Cs = reinterpret_cast<float*>(smem);
    const int gid = lane >> 2, tig = lane & 3;
#pragma unroll
    for (int mt = 0; mt < 2; mt++)
#pragma unroll
        for (int nt = 0; nt < 4; nt++) {
            int col = n_w + nt * 8 + tig * 2;
#pragma unroll
            for (int half = 0; half < 2; half++) {
                int r = m_w + mt * 16 + gid + half * 8;
                Cs[r * 132 + col]     = acc[mt][nt][half * 2 + 0];
                Cs[r * 132 + col + 1] = acc[mt][nt][half * 2 + 1];
            }
        }
    __syncthreads();

    // out[m][4p+h] = Cs[(mm*4+h)][p] + bias[4p+h], float4 over h
    const int mo0 = blockIdx.y * 32;
#pragma unroll
    for (int i = 0; i < 8; i++) {
        int li = tid + i * 512;               // 0..4095
        int p  = li & 127, mm = li >> 7;      // mm 0..31
        float4 b4 = *reinterpret_cast<const float4*>(bias + (size_t)(p0 + p) * 4);
        float4 v;
        v.x = Cs[(mm * 4 + 0) * 132 + p] + b4.x;
        v.y = Cs[(mm * 4 + 1) * 132 + p] + b4.y;
        v.z = Cs[(mm * 4 + 2) * 132 + p] + b4.z;
        v.w = Cs[(mm * 4 + 3) * 132 + p] + b4.w;
        *reinterpret_cast<float4*>(out + (size_t)(mo0 + mm) * 4096 + (size_t)(p0 + p) * 4) = v;
    }
}

// ---------------------------------------------------------------------------
extern "C" void kernel_launch(void* const* d_in, const int* in_sizes, int n_in,
                              void* d_out, int out_size) {
    (void)in_sizes; (void)n_in; (void)out_size;
    const float* x     = (const float*)d_in[0];
    const float* core0 = (const float*)d_in[1];
    const float* core1 = (const float*)d_in[2];
    const float* core2 = (const float*)d_in[3];
    const float* core3 = (const float*)d_in[4];
    const float* bias  = (const float*)d_in[5];
    float* out = (float*)d_out;

    __nv_bfloat16 *T2hi, *T2lo, *Mhi, *Mlo, *Xhi, *Xlo, *Zhi, *Zlo;
    cudaGetSymbolAddress((void**)&T2hi, g_T2hi);
    cudaGetSymbolAddress((void**)&T2lo, g_T2lo);
    cudaGetSymbolAddress((void**)&Mhi,  g_M23thi);
    cudaGetSymbolAddress((void**)&Mlo,  g_M23tlo);
    cudaGetSymbolAddress((void**)&Xhi,  g_Xhi);
    cudaGetSymbolAddress((void**)&Xlo,  g_Xlo);
    cudaGetSymbolAddress((void**)&Zhi,  g_Zhi);
    cudaGetSymbolAddress((void**)&Zlo,  g_Zlo);

    cudaFuncSetAttribute(gemm1_mma, cudaFuncAttributeMaxDynamicSharedMemorySize, SMEMSZ);
    cudaFuncSetAttribute(gemm2_mma, cudaFuncAttributeMaxDynamicSharedMemorySize, SMEMSZ);

    t2_split_kernel  <<<1024, 256>>>(core0, core1, T2hi, T2lo);
    m23t_split_kernel<<<4096, 256>>>(core2, core3, Mhi, Mlo);
    x_split_kernel   <<<8192, 256>>>(x, Xhi, Xlo);

    // GEMM1: Z = X @ M23t^T   grid (n-tiles 8, m-tiles 64)
    gemm1_mma<<<dim3(8, 64), 512, SMEMSZ>>>(Xhi, Xlo, Mhi, Mlo, Zhi, Zlo);

    // GEMM2: out = Z2 @ T2^T + bias   grid (p-tiles 8, row-tiles 256)
    gemm2_mma<<<dim3(8, 256), 512, SMEMSZ>>>(Zhi, Zlo, T2hi, T2lo, bias, out);
}